// round 5
// baseline (speedup 1.0000x reference)
#include <cuda_runtime.h>

// idf-weighted masked mean pooling:
//   out[b,d] = sum_l hidden[b,l,d] * (mask[b,l] ? idf[ids[b,l]] : 0) / max(sum_l mask[b,l], 1e-9)
// hidden [4096, 100, 768] fp32 — 1.26 GB streamed once; HBM/LTS-bound.
// Split each row into 2 half-row CTAs (384 D-columns each) for finer tail granularity.
#define B_SZ   4096
#define L_SZ   100
#define D_SZ   768
#define THREADS 96           // half-row: 96 float4 lanes = 384 floats
#define ROW_F4  (D_SZ / 4)   // 192 float4 per token row

__global__ __launch_bounds__(THREADS, 16)
void sbert_idf_pool_kernel(const float* __restrict__ hidden,
                           const int*   __restrict__ ids,
                           const int*   __restrict__ mask,
                           const float* __restrict__ idf,
                           float*       __restrict__ out) {
    __shared__ float wm[L_SZ];
    __shared__ int   s_cnt;

    const int b    = blockIdx.x >> 1;
    const int half = blockIdx.x & 1;
    const int tid  = threadIdx.x;

    // ---- gather: 96 threads cover 100 tokens (threads 0-3 take two) -------
    if (tid == 0) s_cnt = 0;
    int cnt = 0;
    #pragma unroll
    for (int l = tid; l < L_SZ; l += THREADS) {
        const int m  = __ldg(&mask[b * L_SZ + l]);
        float w = 0.0f;
        if (m != 0) {
            w = __ldg(&idf[__ldg(&ids[b * L_SZ + l])]);
            cnt++;
        }
        wm[l] = w;
    }
    __syncthreads();                       // s_cnt=0 visible
    cnt = __reduce_add_sync(0xffffffffu, cnt);
    if ((tid & 31) == 0) atomicAdd(&s_cnt, cnt);
    __syncthreads();                       // wm[] + s_cnt complete
    const float inv = 1.0f / fmaxf((float)s_cnt, 1e-9f);

    // ---- mainloop: stream 100 x 1536B contiguous half-rows, float4 --------
    const float4* __restrict__ h =
        reinterpret_cast<const float4*>(hidden + (long long)b * (L_SZ * D_SZ))
        + half * THREADS + tid;

    float4 a0 = make_float4(0.f, 0.f, 0.f, 0.f);
    float4 a1 = a0, a2 = a0, a3 = a0;

    #pragma unroll
    for (int l = 0; l < L_SZ; l += 4) {
        const float w0 = wm[l + 0];
        const float w1 = wm[l + 1];
        const float w2 = wm[l + 2];
        const float w3 = wm[l + 3];
        const float4 g0 = h[(l + 0) * ROW_F4];
        const float4 g1 = h[(l + 1) * ROW_F4];
        const float4 g2 = h[(l + 2) * ROW_F4];
        const float4 g3 = h[(l + 3) * ROW_F4];
        a0.x = fmaf(g0.x, w0, a0.x); a0.y = fmaf(g0.y, w0, a0.y);
        a0.z = fmaf(g0.z, w0, a0.z); a0.w = fmaf(g0.w, w0, a0.w);
        a1.x = fmaf(g1.x, w1, a1.x); a1.y = fmaf(g1.y, w1, a1.y);
        a1.z = fmaf(g1.z, w1, a1.z); a1.w = fmaf(g1.w, w1, a1.w);
        a2.x = fmaf(g2.x, w2, a2.x); a2.y = fmaf(g2.y, w2, a2.y);
        a2.z = fmaf(g2.z, w2, a2.z); a2.w = fmaf(g2.w, w2, a2.w);
        a3.x = fmaf(g3.x, w3, a3.x); a3.y = fmaf(g3.y, w3, a3.y);
        a3.z = fmaf(g3.z, w3, a3.z); a3.w = fmaf(g3.w, w3, a3.w);
    }

    float4 r;
    r.x = (a0.x + a1.x + a2.x + a3.x) * inv;
    r.y = (a0.y + a1.y + a2.y + a3.y) * inv;
    r.z = (a0.z + a1.z + a2.z + a3.z) * inv;
    r.w = (a0.w + a1.w + a2.w + a3.w) * inv;

    reinterpret_cast<float4*>(out)[b * ROW_F4 + half * THREADS + tid] = r;
}

extern "C" void kernel_launch(void* const* d_in, const int* in_sizes, int n_in,
                              void* d_out, int out_size) {
    const float* hidden = (const float*)d_in[0];
    const int*   ids    = (const int*)  d_in[1];
    const int*   mask   = (const int*)  d_in[2];
    const float* idf    = (const float*)d_in[3];
    float*       out    = (float*)d_out;

    sbert_idf_pool_kernel<<<B_SZ * 2, THREADS>>>(hidden, ids, mask, idf, out);
}

// round 6
// speedup vs baseline: 1.6876x; 1.6876x over previous
#include <cuda_runtime.h>

// idf-weighted masked mean pooling:
//   out[b,d] = sum_l hidden[b,l,d] * (mask[b,l] ? idf[ids[b,l]] : 0) / max(sum_l mask[b,l], 1e-9)
// KEY: mask is Bernoulli(0.5) -> ~half the tokens have weight 0 and their
// 3072B hidden rows need not be loaded at all. Compact active tokens, then
// stream only those rows. Expected hidden traffic: 1258 MB -> ~630 MB.
#define B_SZ    4096
#define L_SZ    100
#define D_SZ    768
#define THREADS 192          // D/4 float4 lanes
#define ROW_F4  (D_SZ / 4)   // 192
#define NPAD_MAX 104         // L_SZ rounded up to multiple of 4

__global__ __launch_bounds__(THREADS, 8)
void sbert_idf_pool_kernel(const float* __restrict__ hidden,
                           const int*   __restrict__ ids,
                           const int*   __restrict__ mask,
                           const float* __restrict__ idf,
                           float*       __restrict__ out) {
    __shared__ float    sw[NPAD_MAX];     // compacted weights
    __shared__ int      sidx[NPAD_MAX];   // compacted token indices
    __shared__ unsigned sbal[4];          // per-warp activity ballots

    const int b    = blockIdx.x;
    const int tid  = threadIdx.x;
    const int wid  = tid >> 5;
    const int lane = tid & 31;

    // init pad region (idx=0, w=0 dummies are harmless: fma with w=0)
    if (tid < NPAD_MAX) { sw[tid] = 0.0f; sidx[tid] = 0; }

    // ---- per-token gather -------------------------------------------------
    int   m = 0;
    float w = 0.0f;
    if (tid < L_SZ) {
        m = __ldg(&mask[b * L_SZ + tid]);
        if (m != 0) w = __ldg(&idf[__ldg(&ids[b * L_SZ + tid])]);
    }
    const unsigned act = __ballot_sync(0xffffffffu, m != 0);
    if (wid < 4 && lane == 0) sbal[wid] = act;
    __syncthreads();                               // init + ballots visible

    const unsigned b0 = sbal[0], b1 = sbal[1], b2 = sbal[2], b3 = sbal[3];
    const int nact = __popc(b0) + __popc(b1) + __popc(b2) + __popc(b3);

    // ---- stream compaction: active tokens -> sidx/sw -----------------------
    if (m != 0) {
        int pos = __popc(act & ((1u << lane) - 1u));
        if (wid >= 1) pos += __popc(b0);
        if (wid >= 2) pos += __popc(b1);
        if (wid >= 3) pos += __popc(b2);
        sidx[pos] = tid;
        sw[pos]   = w;
    }
    __syncthreads();                               // compaction visible

    const float inv  = 1.0f / fmaxf((float)nact, 1e-9f);
    const int   npad = (nact + 3) & ~3;

    // ---- mainloop: stream ONLY active 3072B rows, float4, 4-way unrolled ---
    const float4* __restrict__ h =
        reinterpret_cast<const float4*>(hidden + (long long)b * (L_SZ * D_SZ)) + tid;

    float4 a0 = make_float4(0.f, 0.f, 0.f, 0.f);
    float4 a1 = a0, a2 = a0, a3 = a0;

    for (int j = 0; j < npad; j += 4) {
        const int   i0 = sidx[j + 0], i1 = sidx[j + 1];
        const int   i2 = sidx[j + 2], i3 = sidx[j + 3];
        const float w0 = sw[j + 0], w1 = sw[j + 1];
        const float w2 = sw[j + 2], w3 = sw[j + 3];
        const float4 g0 = h[i0 * ROW_F4];
        const float4 g1 = h[i1 * ROW_F4];
        const float4 g2 = h[i2 * ROW_F4];
        const float4 g3 = h[i3 * ROW_F4];
        a0.x = fmaf(g0.x, w0, a0.x); a0.y = fmaf(g0.y, w0, a0.y);
        a0.z = fmaf(g0.z, w0, a0.z); a0.w = fmaf(g0.w, w0, a0.w);
        a1.x = fmaf(g1.x, w1, a1.x); a1.y = fmaf(g1.y, w1, a1.y);
        a1.z = fmaf(g1.z, w1, a1.z); a1.w = fmaf(g1.w, w1, a1.w);
        a2.x = fmaf(g2.x, w2, a2.x); a2.y = fmaf(g2.y, w2, a2.y);
        a2.z = fmaf(g2.z, w2, a2.z); a2.w = fmaf(g2.w, w2, a2.w);
        a3.x = fmaf(g3.x, w3, a3.x); a3.y = fmaf(g3.y, w3, a3.y);
        a3.z = fmaf(g3.z, w3, a3.z); a3.w = fmaf(g3.w, w3, a3.w);
    }

    float4 r;
    r.x = (a0.x + a1.x + a2.x + a3.x) * inv;
    r.y = (a0.y + a1.y + a2.y + a3.y) * inv;
    r.z = (a0.z + a1.z + a2.z + a3.z) * inv;
    r.w = (a0.w + a1.w + a2.w + a3.w) * inv;

    reinterpret_cast<float4*>(out)[b * ROW_F4 + tid] = r;
}

extern "C" void kernel_launch(void* const* d_in, const int* in_sizes, int n_in,
                              void* d_out, int out_size) {
    const float* hidden = (const float*)d_in[0];
    const int*   ids    = (const int*)  d_in[1];
    const int*   mask   = (const int*)  d_in[2];
    const float* idf    = (const float*)d_in[3];
    float*       out    = (float*)d_out;

    sbert_idf_pool_kernel<<<B_SZ, THREADS>>>(hidden, ids, mask, idf, out);
}

// round 7
// speedup vs baseline: 1.7425x; 1.0325x over previous
#include <cuda_runtime.h>

// idf-weighted masked mean pooling with active-token compaction:
//   out[b,d] = sum_{l active} hidden[b,l,d] * idf[ids[b,l]] / max(nact, 1e-9)
// mask ~ Bernoulli(0.5): only ~50 of 100 rows per batch are loaded (~650 MB total).
// This round: 8-wide load body (MLP=8/warp) + packed smem (offset,weight) entries.
#define B_SZ    4096
#define L_SZ    100
#define D_SZ    768
#define THREADS 192          // D/4 float4 lanes
#define ROW_F4  (D_SZ / 4)   // 192
#define NPAD_MAX 104         // >= L_SZ rounded up to multiple of 8

__global__ __launch_bounds__(THREADS, 6)
void sbert_idf_pool_kernel(const float* __restrict__ hidden,
                           const int*   __restrict__ ids,
                           const int*   __restrict__ mask,
                           const float* __restrict__ idf,
                           float*       __restrict__ out) {
    __shared__ float2   siw[NPAD_MAX];    // {f4-offset as int bits, weight}
    __shared__ unsigned sbal[4];          // per-warp activity ballots

    const int b    = blockIdx.x;
    const int tid  = threadIdx.x;
    const int wid  = tid >> 5;
    const int lane = tid & 31;

    // pad entries: offset 0, weight 0 (fma-by-zero on row 0 is harmless)
    if (tid < NPAD_MAX) siw[tid] = make_float2(__int_as_float(0), 0.0f);

    // ---- per-token gather -------------------------------------------------
    int   m = 0;
    float w = 0.0f;
    if (tid < L_SZ) {
        m = __ldg(&mask[b * L_SZ + tid]);
        if (m != 0) w = __ldg(&idf[__ldg(&ids[b * L_SZ + tid])]);
    }
    const unsigned act = __ballot_sync(0xffffffffu, m != 0);
    if (wid < 4 && lane == 0) sbal[wid] = act;
    __syncthreads();                               // init + ballots visible

    const unsigned b0 = sbal[0], b1 = sbal[1], b2 = sbal[2], b3 = sbal[3];
    const int nact = __popc(b0) + __popc(b1) + __popc(b2) + __popc(b3);

    // ---- stream compaction: active tokens -> siw (offset pre-scaled) -------
    if (m != 0) {
        int pos = __popc(act & ((1u << lane) - 1u));
        if (wid >= 1) pos += __popc(b0);
        if (wid >= 2) pos += __popc(b1);
        if (wid >= 3) pos += __popc(b2);
        siw[pos] = make_float2(__int_as_float(tid * ROW_F4), w);
    }
    __syncthreads();                               // compaction visible

    const float inv  = 1.0f / fmaxf((float)nact, 1e-9f);
    const int   npad = (nact + 7) & ~7;

    // ---- mainloop: 8 outstanding LDG.128 per body --------------------------
    const float4* __restrict__ h =
        reinterpret_cast<const float4*>(hidden + (long long)b * (L_SZ * D_SZ)) + tid;

    float4 a0 = make_float4(0.f, 0.f, 0.f, 0.f);
    float4 a1 = a0, a2 = a0, a3 = a0;

    for (int j = 0; j < npad; j += 8) {
        const float2 e0 = siw[j + 0], e1 = siw[j + 1];
        const float2 e2 = siw[j + 2], e3 = siw[j + 3];
        const float2 e4 = siw[j + 4], e5 = siw[j + 5];
        const float2 e6 = siw[j + 6], e7 = siw[j + 7];
        // 8 independent loads, all issued before the first consuming FMA
        const float4 g0 = h[__float_as_int(e0.x)];
        const float4 g1 = h[__float_as_int(e1.x)];
        const float4 g2 = h[__float_as_int(e2.x)];
        const float4 g3 = h[__float_as_int(e3.x)];
        const float4 g4 = h[__float_as_int(e4.x)];
        const float4 g5 = h[__float_as_int(e5.x)];
        const float4 g6 = h[__float_as_int(e6.x)];
        const float4 g7 = h[__float_as_int(e7.x)];

        a0.x = fmaf(g0.x, e0.y, a0.x); a0.y = fmaf(g0.y, e0.y, a0.y);
        a0.z = fmaf(g0.z, e0.y, a0.z); a0.w = fmaf(g0.w, e0.y, a0.w);
        a1.x = fmaf(g1.x, e1.y, a1.x); a1.y = fmaf(g1.y, e1.y, a1.y);
        a1.z = fmaf(g1.z, e1.y, a1.z); a1.w = fmaf(g1.w, e1.y, a1.w);
        a2.x = fmaf(g2.x, e2.y, a2.x); a2.y = fmaf(g2.y, e2.y, a2.y);
        a2.z = fmaf(g2.z, e2.y, a2.z); a2.w = fmaf(g2.w, e2.y, a2.w);
        a3.x = fmaf(g3.x, e3.y, a3.x); a3.y = fmaf(g3.y, e3.y, a3.y);
        a3.z = fmaf(g3.z, e3.y, a3.z); a3.w = fmaf(g3.w, e3.y, a3.w);

        a0.x = fmaf(g4.x, e4.y, a0.x); a0.y = fmaf(g4.y, e4.y, a0.y);
        a0.z = fmaf(g4.z, e4.y, a0.z); a0.w = fmaf(g4.w, e4.y, a0.w);
        a1.x = fmaf(g5.x, e5.y, a1.x); a1.y = fmaf(g5.y, e5.y, a1.y);
        a1.z = fmaf(g5.z, e5.y, a1.z); a1.w = fmaf(g5.w, e5.y, a1.w);
        a2.x = fmaf(g6.x, e6.y, a2.x); a2.y = fmaf(g6.y, e6.y, a2.y);
        a2.z = fmaf(g6.z, e6.y, a2.z); a2.w = fmaf(g6.w, e6.y, a2.w);
        a3.x = fmaf(g7.x, e7.y, a3.x); a3.y = fmaf(g7.y, e7.y, a3.y);
        a3.z = fmaf(g7.z, e7.y, a3.z); a3.w = fmaf(g7.w, e7.y, a3.w);
    }

    float4 r;
    r.x = (a0.x + a1.x + a2.x + a3.x) * inv;
    r.y = (a0.y + a1.y + a2.y + a3.y) * inv;
    r.z = (a0.z + a1.z + a2.z + a3.z) * inv;
    r.w = (a0.w + a1.w + a2.w + a3.w) * inv;

    reinterpret_cast<float4*>(out)[b * ROW_F4 + tid] = r;
}

extern "C" void kernel_launch(void* const* d_in, const int* in_sizes, int n_in,
                              void* d_out, int out_size) {
    const float* hidden = (const float*)d_in[0];
    const int*   ids    = (const int*)  d_in[1];
    const int*   mask   = (const int*)  d_in[2];
    const float* idf    = (const float*)d_in[3];
    float*       out    = (float*)d_out;

    sbert_idf_pool_kernel<<<B_SZ, THREADS>>>(hidden, ids, mask, idf, out);
}